// round 5
// baseline (speedup 1.0000x reference)
#include <cuda_runtime.h>
#include <cuda_bf16.h>
#include <cstdint>

#define BN   32
#define SEQ  577
#define CH   768
#define NH   12
#define DH   64
#define MROWS (BN*SEQ)      /* 18464 */
#define QKV_N (3*CH)        /* 2304  */
#define QT   128
#define KT   128
#define NKT  5              /* ceil(577/128) */

// ---------------- scratch (__device__ globals; no allocs allowed) ----------
__device__ __nv_bfloat16 g_qh[BN*NH*SEQ*DH], g_ql[BN*NH*SEQ*DH];
__device__ __nv_bfloat16 g_kh[BN*NH*SEQ*DH], g_kl[BN*NH*SEQ*DH];
__device__ __nv_bfloat16 g_vh[BN*NH*SEQ*DH], g_vl[BN*NH*SEQ*DH];
__device__ __nv_bfloat16 g_xh[MROWS*CH], g_xl[MROWS*CH];   // A hi/lo (x, then attn out)
__device__ __nv_bfloat16 g_wh[QKV_N*CH], g_wl[QKV_N*CH];   // qkv_w hi/lo
__device__ __nv_bfloat16 g_ph[CH*CH],   g_pl[CH*CH];       // proj_w hi/lo

// ---------------- helpers ---------------------------------------------------
__device__ __forceinline__ uint32_t smem_u32(const void* p) {
    uint32_t a;
    asm("{ .reg .u64 t; cvta.to.shared.u64 t, %1; cvt.u32.u64 %0, t; }" : "=r"(a) : "l"(p));
    return a;
}
__device__ __forceinline__ void cpa16(uint32_t dst, const void* src) {
    asm volatile("cp.async.cg.shared.global [%0], [%1], 16;" :: "r"(dst), "l"(src) : "memory");
}
#define CP_COMMIT() asm volatile("cp.async.commit_group;" ::: "memory")
#define CP_WAIT(N)  asm volatile("cp.async.wait_group %0;" :: "n"(N) : "memory")

__device__ __forceinline__ void ldsm_x4(uint32_t& r0, uint32_t& r1,
                                        uint32_t& r2, uint32_t& r3, uint32_t addr) {
    asm volatile("ldmatrix.sync.aligned.m8n8.x4.shared.b16 {%0,%1,%2,%3}, [%4];"
                 : "=r"(r0), "=r"(r1), "=r"(r2), "=r"(r3) : "r"(addr));
}
__device__ __forceinline__ void ldsm_x4_t(uint32_t& r0, uint32_t& r1,
                                          uint32_t& r2, uint32_t& r3, uint32_t addr) {
    asm volatile("ldmatrix.sync.aligned.m8n8.x4.trans.shared.b16 {%0,%1,%2,%3}, [%4];"
                 : "=r"(r0), "=r"(r1), "=r"(r2), "=r"(r3) : "r"(addr));
}
__device__ __forceinline__ void mma16816(float* c, const uint32_t* a, const uint32_t* b) {
    asm volatile("mma.sync.aligned.m16n8k16.row.col.f32.bf16.bf16.f32 "
                 "{%0,%1,%2,%3}, {%4,%5,%6,%7}, {%8,%9}, {%0,%1,%2,%3};"
                 : "+f"(c[0]), "+f"(c[1]), "+f"(c[2]), "+f"(c[3])
                 : "r"(a[0]), "r"(a[1]), "r"(a[2]), "r"(a[3]), "r"(b[0]), "r"(b[1]));
}
__device__ __forceinline__ void mma2(float* c, const uint32_t* a, uint32_t b0, uint32_t b1) {
    asm volatile("mma.sync.aligned.m16n8k16.row.col.f32.bf16.bf16.f32 "
                 "{%0,%1,%2,%3}, {%4,%5,%6,%7}, {%8,%9}, {%0,%1,%2,%3};"
                 : "+f"(c[0]), "+f"(c[1]), "+f"(c[2]), "+f"(c[3])
                 : "r"(a[0]), "r"(a[1]), "r"(a[2]), "r"(a[3]), "r"(b0), "r"(b1));
}
// GEMM tile swizzle: 64B rows, 4 chunks
__device__ __forceinline__ uint32_t swoff(int r, int c) {
    return (uint32_t)(r * 64 + ((c ^ ((r >> 1) & 3)) << 4));
}
// attention tile swizzle: 128B rows, 8 chunks
__device__ __forceinline__ uint32_t aswz(int r, int c) {
    return (uint32_t)(r * 128 + ((c ^ (r & 7)) << 4));
}
// fp32 pair -> bf16 hi pair + bf16 lo pair (packed u32)
__device__ __forceinline__ void split2(float x, float y, uint32_t& hi, uint32_t& lo) {
    __nv_bfloat162 h2 = __floats2bfloat162_rn(x, y);
    __nv_bfloat162 l2 = __floats2bfloat162_rn(x - __bfloat162float(h2.x),
                                              y - __bfloat162float(h2.y));
    hi = reinterpret_cast<uint32_t&>(h2);
    lo = reinterpret_cast<uint32_t&>(l2);
}

// ---------------- split: fp32 -> bf16 hi + bf16 lo -------------------------
__global__ void split_kernel(const float* __restrict__ src, int sel, int n) {
    int i = blockIdx.x * 256 + threadIdx.x;
    if (i >= n) return;
    float v = src[i];
    __nv_bfloat16 h = __float2bfloat16(v);
    __nv_bfloat16 l = __float2bfloat16(v - __bfloat162float(h));
    if (sel == 0)      { g_xh[i] = h; g_xl[i] = l; }
    else if (sel == 1) { g_wh[i] = h; g_wl[i] = l; }
    else               { g_ph[i] = h; g_pl[i] = l; }
}

// ---------------- mma.sync bf16x3 GEMM, cp.async 2-stage --------------------
// MODE 0: A=x(split), B=qkv_w(split) -> g_{q,k,v}{h,l} bf16 (+bias, q*0.125)
// MODE 1: A=attn-out(split in g_x{h,l}), B=proj_w(split) -> out (+bias)
#define G_STAGE 32768
#define G_SMEM  (2*G_STAGE)

template<int MODE>
__global__ __launch_bounds__(256) void mma_gemm(const float* __restrict__ bias,
                                                float* __restrict__ out)
{
    extern __shared__ __align__(16) char smem[];
    const uint32_t sb = smem_u32(smem);
    const int tid = threadIdx.x, lane = tid & 31, wid = tid >> 5;
    const int wm = wid & 1, wn = wid >> 1;
    const int tileN = blockIdx.x, tileM = blockIdx.y;

    const __nv_bfloat16* __restrict__ Ah = g_xh;
    const __nv_bfloat16* __restrict__ Al = g_xl;
    const __nv_bfloat16* __restrict__ Bh = (MODE == 0) ? g_wh : g_ph;
    const __nv_bfloat16* __restrict__ Bl = (MODE == 0) ? g_wl : g_pl;

    // per-stage buffer offsets
    const uint32_t OFF_AH = 0, OFF_AL = 8192, OFF_BH = 16384, OFF_BL = 24576;

    // loader mapping: 2 x 16B chunks per thread per buffer
    const int lr = tid >> 1;
    const int lc = (tid & 1) << 1;
    int ga = tileM * 128 + lr; if (ga > MROWS - 1) ga = MROWS - 1;
    const int gb = tileN * 128 + lr;
    const size_t abase = (size_t)ga * CH + lc * 8;
    const size_t bbase = (size_t)gb * CH + lc * 8;
    const uint32_t so0 = swoff(lr, lc), so1 = swoff(lr, lc + 1);

    float acc[4][4][4];
    #pragma unroll
    for (int i = 0; i < 4; ++i)
        #pragma unroll
        for (int j = 0; j < 4; ++j)
            #pragma unroll
            for (int r = 0; r < 4; ++r) acc[i][j][r] = 0.f;

    // prologue: stage 0 loads (chunk 0)
    {
        const uint32_t st = sb;
        cpa16(st + OFF_AH + so0, Ah + abase);      cpa16(st + OFF_AH + so1, Ah + abase + 8);
        cpa16(st + OFF_AL + so0, Al + abase);      cpa16(st + OFF_AL + so1, Al + abase + 8);
        cpa16(st + OFF_BH + so0, Bh + bbase);      cpa16(st + OFF_BH + so1, Bh + bbase + 8);
        cpa16(st + OFF_BL + so0, Bl + bbase);      cpa16(st + OFF_BL + so1, Bl + bbase + 8);
        CP_COMMIT();
    }

    for (int kc = 0; kc < 24; ++kc) {
        if (kc + 1 < 24) {   // issue loads for kc+1 into other stage
            const uint32_t st = sb + ((kc + 1) & 1) * G_STAGE;
            const size_t ao = abase + (size_t)(kc + 1) * 32;
            const size_t bo = bbase + (size_t)(kc + 1) * 32;
            cpa16(st + OFF_AH + so0, Ah + ao);     cpa16(st + OFF_AH + so1, Ah + ao + 8);
            cpa16(st + OFF_AL + so0, Al + ao);     cpa16(st + OFF_AL + so1, Al + ao + 8);
            cpa16(st + OFF_BH + so0, Bh + bo);     cpa16(st + OFF_BH + so1, Bh + bo + 8);
            cpa16(st + OFF_BL + so0, Bl + bo);     cpa16(st + OFF_BL + so1, Bl + bo + 8);
            CP_COMMIT();
            CP_WAIT(1);      // stage kc complete, stage kc+1 in flight
        } else {
            CP_WAIT(0);
        }
        __syncthreads();

        const uint32_t st = sb + (kc & 1) * G_STAGE;
        #pragma unroll
        for (int k16 = 0; k16 < 2; ++k16) {
            uint32_t ah[4][4], al[4][4];
            #pragma unroll
            for (int mf = 0; mf < 4; ++mf) {
                int row = wm * 64 + mf * 16 + (lane & 15);
                int c   = 2 * k16 + (lane >> 4);
                uint32_t o = swoff(row, c);
                ldsm_x4(ah[mf][0], ah[mf][1], ah[mf][2], ah[mf][3], st + OFF_AH + o);
                ldsm_x4(al[mf][0], al[mf][1], al[mf][2], al[mf][3], st + OFF_AL + o);
            }
            uint32_t bh[4][2], bl[4][2];
            #pragma unroll
            for (int np = 0; np < 2; ++np) {
                int g = lane >> 3, l = lane & 7;
                int row = wn * 32 + np * 16 + (g >> 1) * 8 + l;
                int c   = 2 * k16 + (g & 1);
                uint32_t o = swoff(row, c);
                ldsm_x4(bh[np*2][0], bh[np*2][1], bh[np*2+1][0], bh[np*2+1][1],
                        st + OFF_BH + o);
                ldsm_x4(bl[np*2][0], bl[np*2][1], bl[np*2+1][0], bl[np*2+1][1],
                        st + OFF_BL + o);
            }
            #pragma unroll
            for (int mf = 0; mf < 4; ++mf)
                #pragma unroll
                for (int nf = 0; nf < 4; ++nf) {
                    mma16816(acc[mf][nf], ah[mf], bh[nf]);
                    mma16816(acc[mf][nf], ah[mf], bl[nf]);
                    mma16816(acc[mf][nf], al[mf], bh[nf]);
                }
        }
        __syncthreads();   // all reads of this stage done before it is refilled
    }

    // ---------------- epilogue ----------------
    const int s = (MODE == 0) ? (tileN * 128) / CH : 0;
    const float scl = (MODE == 0 && s == 0) ? 0.125f : 1.0f;

    #pragma unroll
    for (int mf = 0; mf < 4; ++mf) {
        const int rbase = tileM * 128 + wm * 64 + mf * 16 + (lane >> 2);
        #pragma unroll
        for (int nf = 0; nf < 4; ++nf) {
            const int gcol = tileN * 128 + wn * 32 + nf * 8 + ((lane & 3) << 1);
            const float b0 = bias[gcol], b1 = bias[gcol + 1];
            #pragma unroll
            for (int hh = 0; hh < 2; ++hh) {
                const int row = rbase + hh * 8;
                if (row >= MROWS) continue;
                float v0 = (acc[mf][nf][hh*2+0] + b0) * scl;
                float v1 = (acc[mf][nf][hh*2+1] + b1) * scl;
                if (MODE == 0) {
                    int rem = gcol - s * CH;
                    int hd = rem >> 6, d = rem & 63;
                    int bb = row / SEQ, n = row - bb * SEQ;
                    size_t di = ((size_t)(bb * NH + hd) * SEQ + n) * DH + d;
                    __nv_bfloat16 *dsth, *dstl;
                    if (s == 0)      { dsth = g_qh; dstl = g_ql; }
                    else if (s == 1) { dsth = g_kh; dstl = g_kl; }
                    else             { dsth = g_vh; dstl = g_vl; }
                    uint32_t hp, lp;
                    split2(v0, v1, hp, lp);
                    *(uint32_t*)(dsth + di) = hp;
                    *(uint32_t*)(dstl + di) = lp;
                } else {
                    *(float2*)(out + (size_t)row * CH + gcol) = make_float2(v0, v1);
                }
            }
        }
    }
}

// ---------------- mma.sync flash attention, cp.async 2-stage K/V ------------
#define ATT_QH 0
#define ATT_QL 16384
#define ATT_ST 32768          /* stage base */
#define ATT_STAGE 65536       /* KH, KL, VH, VL each 16 KB */
#define A_KH 0
#define A_KL 16384
#define A_VH 32768
#define A_VL 49152
#define ATT_SMEM (ATT_ST + 2*ATT_STAGE)   /* 163840 */

__global__ __launch_bounds__(256) void attn_mma()
{
    extern __shared__ __align__(16) char sm[];
    const uint32_t sb = smem_u32(sm);
    const int tid = threadIdx.x, lane = tid & 31, w = tid >> 5;
    const int q0 = blockIdx.x * QT;
    const int hh = blockIdx.y, b = blockIdx.z;
    const size_t hb = (size_t)(b * NH + hh) * SEQ;

    // load Q tile (hi/lo), swizzled (plain loads — once per block)
    #pragma unroll
    for (int p = 0; p < 4; ++p) {
        int slot = tid + p * 256;
        int r = slot >> 3, c = slot & 7;
        int gr = q0 + r; if (gr > SEQ - 1) gr = SEQ - 1;
        size_t idx = ((hb + gr) << 6) + c * 8;
        uint32_t so = aswz(r, c);
        *(int4*)(sm + ATT_QH + so) = *(const int4*)(g_qh + idx);
        *(int4*)(sm + ATT_QL + so) = *(const int4*)(g_ql + idx);
    }

    // prologue: stage 0 K/V loads for tile 0
    #pragma unroll
    for (int p = 0; p < 4; ++p) {
        int slot = tid + p * 256;
        int r = slot >> 3, c = slot & 7;
        int gk = r; if (gk > SEQ - 1) gk = SEQ - 1;
        size_t idx = ((hb + gk) << 6) + c * 8;
        uint32_t so = aswz(r, c);
        const uint32_t st = sb + ATT_ST;
        cpa16(st + A_KH + so, g_kh + idx);
        cpa16(st + A_KL + so, g_kl + idx);
        cpa16(st + A_VH + so, g_vh + idx);
        cpa16(st + A_VL + so, g_vl + idx);
    }
    CP_COMMIT();
    __syncthreads();   // Q ready

    // Q fragments in registers (4 k16 steps over DH)
    uint32_t qh[4][4], ql[4][4];
    #pragma unroll
    for (int kd = 0; kd < 4; ++kd) {
        int row = w * 16 + (lane & 15);
        int c = 2 * kd + (lane >> 4);
        uint32_t o = aswz(row, c);
        ldsm_x4(qh[kd][0], qh[kd][1], qh[kd][2], qh[kd][3], sb + ATT_QH + o);
        ldsm_x4(ql[kd][0], ql[kd][1], ql[kd][2], ql[kd][3], sb + ATT_QL + o);
    }

    float o[8][4];
    #pragma unroll
    for (int i = 0; i < 8; ++i)
        #pragma unroll
        for (int j = 0; j < 4; ++j) o[i][j] = 0.f;
    float m0 = -1e30f, m1 = -1e30f, l0 = 0.f, l1 = 0.f;

    for (int kt = 0; kt < NKT; ++kt) {
        const int k0 = kt * KT;
        if (kt + 1 < NKT) {        // prefetch next K/V tile into other stage
            const uint32_t st = sb + ATT_ST + ((kt + 1) & 1) * ATT_STAGE;
            #pragma unroll
            for (int p = 0; p < 4; ++p) {
                int slot = tid + p * 256;
                int r = slot >> 3, c = slot & 7;
                int gk = k0 + KT + r; if (gk > SEQ - 1) gk = SEQ - 1;
                size_t idx = ((hb + gk) << 6) + c * 8;
                uint32_t so = aswz(r, c);
                cpa16(st + A_KH + so, g_kh + idx);
                cpa16(st + A_KL + so, g_kl + idx);
                cpa16(st + A_VH + so, g_vh + idx);
                cpa16(st + A_VL + so, g_vl + idx);
            }
            CP_COMMIT();
            CP_WAIT(1);
        } else {
            CP_WAIT(0);
        }
        __syncthreads();
        const uint32_t st = sb + ATT_ST + (kt & 1) * ATT_STAGE;

        // ---- S = Q K^T ----
        float s[16][4];
        #pragma unroll
        for (int i = 0; i < 16; ++i)
            #pragma unroll
            for (int j = 0; j < 4; ++j) s[i][j] = 0.f;

        #pragma unroll
        for (int kp = 0; kp < 8; ++kp) {
            #pragma unroll
            for (int kd = 0; kd < 4; ++kd) {
                int g = lane >> 3, li = lane & 7;
                int row = kp * 16 + ((g >> 1) << 3) + li;
                int c = 2 * kd + (g & 1);
                uint32_t so = aswz(row, c);
                uint32_t kh4[4], kl4[4];
                ldsm_x4(kh4[0], kh4[1], kh4[2], kh4[3], st + A_KH + so);
                ldsm_x4(kl4[0], kl4[1], kl4[2], kl4[3], st + A_KL + so);
                mma2(s[2*kp],   qh[kd], kh4[0], kh4[1]);
                mma2(s[2*kp],   qh[kd], kl4[0], kl4[1]);
                mma2(s[2*kp],   ql[kd], kh4[0], kh4[1]);
                mma2(s[2*kp+1], qh[kd], kh4[2], kh4[3]);
                mma2(s[2*kp+1], qh[kd], kl4[2], kl4[3]);
                mma2(s[2*kp+1], ql[kd], kh4[2], kh4[3]);
            }
        }

        // mask invalid keys (last tile)
        if (k0 + KT > SEQ) {
            #pragma unroll
            for (int kn = 0; kn < 16; ++kn) {
                int kg = k0 + kn * 8 + ((lane & 3) << 1);
                if (kg >= SEQ)     { s[kn][0] = -1e30f; s[kn][2] = -1e30f; }
                if (kg + 1 >= SEQ) { s[kn][1] = -1e30f; s[kn][3] = -1e30f; }
            }
        }

        // ---- online softmax ----
        float mx0 = -1e30f, mx1 = -1e30f;
        #pragma unroll
        for (int kn = 0; kn < 16; ++kn) {
            mx0 = fmaxf(mx0, fmaxf(s[kn][0], s[kn][1]));
            mx1 = fmaxf(mx1, fmaxf(s[kn][2], s[kn][3]));
        }
        mx0 = fmaxf(mx0, __shfl_xor_sync(0xffffffffu, mx0, 1));
        mx0 = fmaxf(mx0, __shfl_xor_sync(0xffffffffu, mx0, 2));
        mx1 = fmaxf(mx1, __shfl_xor_sync(0xffffffffu, mx1, 1));
        mx1 = fmaxf(mx1, __shfl_xor_sync(0xffffffffu, mx1, 2));
        float mn0 = fmaxf(m0, mx0), mn1 = fmaxf(m1, mx1);
        float c0 = __expf(m0 - mn0), c1 = __expf(m1 - mn1);
        float sum0 = 0.f, sum1 = 0.f;
        #pragma unroll
        for (int kn = 0; kn < 16; ++kn) {
            s[kn][0] = __expf(s[kn][0] - mn0);
            s[kn][1] = __expf(s[kn][1] - mn0);
            s[kn][2] = __expf(s[kn][2] - mn1);
            s[kn][3] = __expf(s[kn][3] - mn1);
            sum0 += s[kn][0] + s[kn][1];
            sum1 += s[kn][2] + s[kn][3];
        }
        sum0 += __shfl_xor_sync(0xffffffffu, sum0, 1);
        sum0 += __shfl_xor_sync(0xffffffffu, sum0, 2);
        sum1 += __shfl_xor_sync(0xffffffffu, sum1, 1);
        sum1 += __shfl_xor_sync(0xffffffffu, sum1, 2);
        l0 = l0 * c0 + sum0; l1 = l1 * c1 + sum1;
        m0 = mn0; m1 = mn1;
        #pragma unroll
        for (int nf = 0; nf < 8; ++nf) {
            o[nf][0] *= c0; o[nf][1] *= c0;
            o[nf][2] *= c1; o[nf][3] *= c1;
        }

        // ---- PV: O += P V  (P packed from S regs) ----
        #pragma unroll
        for (int kk = 0; kk < 8; ++kk) {
            uint32_t ah[4], al[4];
            split2(s[2*kk][0],   s[2*kk][1],   ah[0], al[0]);
            split2(s[2*kk][2],   s[2*kk][3],   ah[1], al[1]);
            split2(s[2*kk+1][0], s[2*kk+1][1], ah[2], al[2]);
            split2(s[2*kk+1][2], s[2*kk+1][3], ah[3], al[3]);
            #pragma unroll
            for (int d16 = 0; d16 < 4; ++d16) {
                int g = lane >> 3, li = lane & 7;
                int row = kk * 16 + ((g & 1) << 3) + li;
                int c = d16 * 2 + (g >> 1);
                uint32_t so = aswz(row, c);
                uint32_t vh4[4], vl4[4];
                ldsm_x4_t(vh4[0], vh4[1], vh4[2], vh4[3], st + A_VH + so);
                ldsm_x4_t(vl4[0], vl4[1], vl4[2], vl4[3], st + A_VL + so);
                mma2(o[2*d16],   ah, vh4[0], vh4[1]);
                mma2(o[2*d16],   al, vh4[0], vh4[1]);
                mma2(o[2*d16],   ah, vl4[0], vl4[1]);
                mma2(o[2*d16+1], ah, vh4[2], vh4[3]);
                mma2(o[2*d16+1], al, vh4[2], vh4[3]);
                mma2(o[2*d16+1], ah, vl4[2], vl4[3]);
            }
        }
        __syncthreads();   // stage reads done before refill
    }

    // ---- epilogue: o/l -> bf16 hi/lo into proj-A buffers ----
    float r0 = 1.f / l0, r1 = 1.f / l1;
    int rg = lane >> 2, t2 = (lane & 3) << 1;
    int row0 = q0 + w * 16 + rg, row1 = row0 + 8;
    #pragma unroll
    for (int nf = 0; nf < 8; ++nf) {
        int col = hh * DH + nf * 8 + t2;
        if (row0 < SEQ) {
            size_t gi = (size_t)(b * SEQ + row0) * CH + col;
            uint32_t hp, lp;
            split2(o[nf][0] * r0, o[nf][1] * r0, hp, lp);
            *(uint32_t*)(g_xh + gi) = hp;
            *(uint32_t*)(g_xl + gi) = lp;
        }
        if (row1 < SEQ) {
            size_t gi = (size_t)(b * SEQ + row1) * CH + col;
            uint32_t hp, lp;
            split2(o[nf][2] * r1, o[nf][3] * r1, hp, lp);
            *(uint32_t*)(g_xh + gi) = hp;
            *(uint32_t*)(g_xl + gi) = lp;
        }
    }
}

// ---------------------------------------------------------------------------
extern "C" void kernel_launch(void* const* d_in, const int* in_sizes, int n_in,
                              void* d_out, int out_size)
{
    const float* x      = (const float*)d_in[0];
    const float* qkv_w  = (const float*)d_in[1];
    const float* qkv_b  = (const float*)d_in[2];
    const float* proj_w = (const float*)d_in[3];
    const float* proj_b = (const float*)d_in[4];
    float* out = (float*)d_out;

    cudaFuncSetAttribute(mma_gemm<0>, cudaFuncAttributeMaxDynamicSharedMemorySize, G_SMEM);
    cudaFuncSetAttribute(mma_gemm<1>, cudaFuncAttributeMaxDynamicSharedMemorySize, G_SMEM);
    cudaFuncSetAttribute(attn_mma, cudaFuncAttributeMaxDynamicSharedMemorySize, ATT_SMEM);

    split_kernel<<<(MROWS*CH + 255)/256, 256>>>(x, 0, MROWS*CH);
    split_kernel<<<(QKV_N*CH + 255)/256, 256>>>(qkv_w, 1, QKV_N*CH);
    split_kernel<<<(CH*CH + 255)/256, 256>>>(proj_w, 2, CH*CH);

    mma_gemm<0><<<dim3(QKV_N/128, (MROWS + 127)/128), 256, G_SMEM>>>(qkv_b, nullptr);

    attn_mma<<<dim3((SEQ + QT - 1)/QT, NH, BN), 256, ATT_SMEM>>>();

    mma_gemm<1><<<dim3(CH/128, (MROWS + 127)/128), 256, G_SMEM>>>(proj_b, out);
}

// round 6
// speedup vs baseline: 1.0683x; 1.0683x over previous
#include <cuda_runtime.h>
#include <cuda_bf16.h>
#include <cstdint>

#define BN   32
#define SEQ  577
#define CH   768
#define NH   12
#define DH   64
#define MROWS (BN*SEQ)      /* 18464 */
#define QKV_N (3*CH)        /* 2304  */
#define QT   128
#define KT   128
#define NKT  5              /* ceil(577/128) */

// ---------------- scratch (__device__ globals; no allocs allowed) ----------
__device__ __nv_bfloat16 g_qh[BN*NH*SEQ*DH], g_ql[BN*NH*SEQ*DH];
__device__ __nv_bfloat16 g_kh[BN*NH*SEQ*DH], g_kl[BN*NH*SEQ*DH];
__device__ __nv_bfloat16 g_vh[BN*NH*SEQ*DH], g_vl[BN*NH*SEQ*DH];
__device__ __nv_bfloat16 g_xh[MROWS*CH], g_xl[MROWS*CH];   // A hi/lo (x, then attn out)
__device__ __nv_bfloat16 g_wh[QKV_N*CH], g_wl[QKV_N*CH];   // qkv_w hi/lo
__device__ __nv_bfloat16 g_ph[CH*CH],   g_pl[CH*CH];       // proj_w hi/lo

// ---------------- helpers ---------------------------------------------------
__device__ __forceinline__ uint32_t smem_u32(const void* p) {
    uint32_t a;
    asm("{ .reg .u64 t; cvta.to.shared.u64 t, %1; cvt.u32.u64 %0, t; }" : "=r"(a) : "l"(p));
    return a;
}
__device__ __forceinline__ void ldsm_x4(uint32_t& r0, uint32_t& r1,
                                        uint32_t& r2, uint32_t& r3, uint32_t addr) {
    asm volatile("ldmatrix.sync.aligned.m8n8.x4.shared.b16 {%0,%1,%2,%3}, [%4];"
                 : "=r"(r0), "=r"(r1), "=r"(r2), "=r"(r3) : "r"(addr));
}
__device__ __forceinline__ void ldsm_x4_t(uint32_t& r0, uint32_t& r1,
                                          uint32_t& r2, uint32_t& r3, uint32_t addr) {
    asm volatile("ldmatrix.sync.aligned.m8n8.x4.trans.shared.b16 {%0,%1,%2,%3}, [%4];"
                 : "=r"(r0), "=r"(r1), "=r"(r2), "=r"(r3) : "r"(addr));
}
__device__ __forceinline__ void mma16816(float* c, const uint32_t* a, const uint32_t* b) {
    asm volatile("mma.sync.aligned.m16n8k16.row.col.f32.bf16.bf16.f32 "
                 "{%0,%1,%2,%3}, {%4,%5,%6,%7}, {%8,%9}, {%0,%1,%2,%3};"
                 : "+f"(c[0]), "+f"(c[1]), "+f"(c[2]), "+f"(c[3])
                 : "r"(a[0]), "r"(a[1]), "r"(a[2]), "r"(a[3]), "r"(b[0]), "r"(b[1]));
}
__device__ __forceinline__ void mma2(float* c, const uint32_t* a, uint32_t b0, uint32_t b1) {
    asm volatile("mma.sync.aligned.m16n8k16.row.col.f32.bf16.bf16.f32 "
                 "{%0,%1,%2,%3}, {%4,%5,%6,%7}, {%8,%9}, {%0,%1,%2,%3};"
                 : "+f"(c[0]), "+f"(c[1]), "+f"(c[2]), "+f"(c[3])
                 : "r"(a[0]), "r"(a[1]), "r"(a[2]), "r"(a[3]), "r"(b0), "r"(b1));
}
// GEMM tile swizzle: 64B rows, 4 chunks
__device__ __forceinline__ uint32_t swoff(int r, int c) {
    return (uint32_t)(r * 64 + ((c ^ ((r >> 1) & 3)) << 4));
}
// attention tile swizzle: 128B rows, 8 chunks
__device__ __forceinline__ uint32_t aswz(int r, int c) {
    return (uint32_t)(r * 128 + ((c ^ (r & 7)) << 4));
}
// fp32 pair -> bf16 hi pair + bf16 lo pair (packed u32)
__device__ __forceinline__ void split2(float x, float y, uint32_t& hi, uint32_t& lo) {
    __nv_bfloat162 h2 = __floats2bfloat162_rn(x, y);
    __nv_bfloat162 l2 = __floats2bfloat162_rn(x - __bfloat162float(h2.x),
                                              y - __bfloat162float(h2.y));
    hi = reinterpret_cast<uint32_t&>(h2);
    lo = reinterpret_cast<uint32_t&>(l2);
}

// ---------------- split: fp32 -> bf16 hi + bf16 lo -------------------------
__global__ void split_kernel(const float* __restrict__ src, int sel, int n) {
    int i = blockIdx.x * 256 + threadIdx.x;
    if (i >= n) return;
    float v = src[i];
    __nv_bfloat16 h = __float2bfloat16(v);
    __nv_bfloat16 l = __float2bfloat16(v - __bfloat162float(h));
    if (sel == 0)      { g_xh[i] = h; g_xl[i] = l; }
    else if (sel == 1) { g_wh[i] = h; g_wl[i] = l; }
    else               { g_ph[i] = h; g_pl[i] = l; }
}

// ---------------- mma.sync bf16x3 GEMM, 512 thr / 16 warps ------------------
// 128x128 tile, warp tile 32x32, single-stage smem + register prefetch.
// MODE 0: A=x(split), B=qkv_w(split) -> g_{q,k,v}{h,l} bf16 (+bias, q*0.125)
// MODE 1: A=attn-out(split in g_x{h,l}), B=proj_w(split) -> out (+bias)
template<int MODE>
__global__ __launch_bounds__(512) void mma_gemm(const float* __restrict__ bias,
                                                float* __restrict__ out)
{
    __shared__ __align__(16) char smem[32768];
    const uint32_t sb = smem_u32(smem);
    const int tid = threadIdx.x, lane = tid & 31, wid = tid >> 5;
    const int wm = wid & 3, wn = wid >> 2;          // 4 x 4 warp grid, 32x32 tiles
    const int tileN = blockIdx.x, tileM = blockIdx.y;

    const __nv_bfloat16* __restrict__ Ah = g_xh;
    const __nv_bfloat16* __restrict__ Al = g_xl;
    const __nv_bfloat16* __restrict__ Bh = (MODE == 0) ? g_wh : g_ph;
    const __nv_bfloat16* __restrict__ Bl = (MODE == 0) ? g_wl : g_pl;

    const uint32_t OFF_AH = 0, OFF_AL = 8192, OFF_BH = 16384, OFF_BL = 24576;

    // loader: 512 threads, one 16B chunk per buffer each (128 rows x 4 chunks)
    const int lr = tid >> 2;            // 0..127
    const int lc = tid & 3;             // 0..3
    int ga = tileM * 128 + lr; if (ga > MROWS - 1) ga = MROWS - 1;
    const int gb = tileN * 128 + lr;
    const size_t abase = (size_t)ga * CH + lc * 8;
    const size_t bbase = (size_t)gb * CH + lc * 8;
    const uint32_t so = swoff(lr, lc);

    float acc[2][4][4];
    #pragma unroll
    for (int i = 0; i < 2; ++i)
        #pragma unroll
        for (int j = 0; j < 4; ++j)
            #pragma unroll
            for (int r = 0; r < 4; ++r) acc[i][j][r] = 0.f;

    int4 pah, pal, pbh, pbl;
    pah = *(const int4*)(Ah + abase);
    pal = *(const int4*)(Al + abase);
    pbh = *(const int4*)(Bh + bbase);
    pbl = *(const int4*)(Bl + bbase);

    for (int kc = 0; kc < 24; ++kc) {
        __syncthreads();                 // prior iter done reading smem
        *(int4*)(smem + OFF_AH + so) = pah;
        *(int4*)(smem + OFF_AL + so) = pal;
        *(int4*)(smem + OFF_BH + so) = pbh;
        *(int4*)(smem + OFF_BL + so) = pbl;
        __syncthreads();

        if (kc + 1 < 24) {               // prefetch next chunk (overlaps HMMAs)
            size_t ao = abase + (size_t)(kc + 1) * 32;
            size_t bo = bbase + (size_t)(kc + 1) * 32;
            pah = *(const int4*)(Ah + ao);
            pal = *(const int4*)(Al + ao);
            pbh = *(const int4*)(Bh + bo);
            pbl = *(const int4*)(Bl + bo);
        }

        #pragma unroll
        for (int k16 = 0; k16 < 2; ++k16) {
            uint32_t ah[2][4], al[2][4];
            #pragma unroll
            for (int mf = 0; mf < 2; ++mf) {
                int row = wm * 32 + mf * 16 + (lane & 15);
                int c   = 2 * k16 + (lane >> 4);
                uint32_t o = swoff(row, c);
                ldsm_x4(ah[mf][0], ah[mf][1], ah[mf][2], ah[mf][3], sb + OFF_AH + o);
                ldsm_x4(al[mf][0], al[mf][1], al[mf][2], al[mf][3], sb + OFF_AL + o);
            }
            uint32_t bh[4][2], bl[4][2];
            #pragma unroll
            for (int np = 0; np < 2; ++np) {
                int g = lane >> 3, l = lane & 7;
                int row = wn * 32 + np * 16 + (g >> 1) * 8 + l;
                int c   = 2 * k16 + (g & 1);
                uint32_t o = swoff(row, c);
                ldsm_x4(bh[np*2][0], bh[np*2][1], bh[np*2+1][0], bh[np*2+1][1],
                        sb + OFF_BH + o);
                ldsm_x4(bl[np*2][0], bl[np*2][1], bl[np*2+1][0], bl[np*2+1][1],
                        sb + OFF_BL + o);
            }
            #pragma unroll
            for (int mf = 0; mf < 2; ++mf)
                #pragma unroll
                for (int nf = 0; nf < 4; ++nf) {
                    mma16816(acc[mf][nf], ah[mf], bh[nf]);
                    mma16816(acc[mf][nf], ah[mf], bl[nf]);
                    mma16816(acc[mf][nf], al[mf], bh[nf]);
                }
        }
    }

    // ---------------- epilogue ----------------
    const int s = (MODE == 0) ? (tileN * 128) / CH : 0;
    const float scl = (MODE == 0 && s == 0) ? 0.125f : 1.0f;

    #pragma unroll
    for (int mf = 0; mf < 2; ++mf) {
        const int rbase = tileM * 128 + wm * 32 + mf * 16 + (lane >> 2);
        #pragma unroll
        for (int nf = 0; nf < 4; ++nf) {
            const int gcol = tileN * 128 + wn * 32 + nf * 8 + ((lane & 3) << 1);
            const float b0 = bias[gcol], b1 = bias[gcol + 1];
            #pragma unroll
            for (int hh = 0; hh < 2; ++hh) {
                const int row = rbase + hh * 8;
                if (row >= MROWS) continue;
                float v0 = (acc[mf][nf][hh*2+0] + b0) * scl;
                float v1 = (acc[mf][nf][hh*2+1] + b1) * scl;
                if (MODE == 0) {
                    int rem = gcol - s * CH;
                    int hd = rem >> 6, d = rem & 63;
                    int bb = row / SEQ, n = row - bb * SEQ;
                    size_t di = ((size_t)(bb * NH + hd) * SEQ + n) * DH + d;
                    __nv_bfloat16 *dsth, *dstl;
                    if (s == 0)      { dsth = g_qh; dstl = g_ql; }
                    else if (s == 1) { dsth = g_kh; dstl = g_kl; }
                    else             { dsth = g_vh; dstl = g_vl; }
                    uint32_t hp, lp;
                    split2(v0, v1, hp, lp);
                    *(uint32_t*)(dsth + di) = hp;
                    *(uint32_t*)(dstl + di) = lp;
                } else {
                    *(float2*)(out + (size_t)row * CH + gcol) = make_float2(v0, v1);
                }
            }
        }
    }
}

// ---------------- mma.sync flash attention (R4 version) ---------------------
#define ATT_QH 0
#define ATT_QL 16384
#define ATT_KH 32768
#define ATT_KL 49152
#define ATT_VH 65536
#define ATT_VL 81920
#define ATT_SMEM 98304

__global__ __launch_bounds__(256) void attn_mma()
{
    extern __shared__ char sm[];
    const uint32_t sb = smem_u32(sm);
    const int tid = threadIdx.x, lane = tid & 31, w = tid >> 5;
    const int q0 = blockIdx.x * QT;
    const int hh = blockIdx.y, b = blockIdx.z;
    const size_t hb = (size_t)(b * NH + hh) * SEQ;

    // load Q tile (hi/lo), swizzled
    #pragma unroll
    for (int p = 0; p < 4; ++p) {
        int slot = tid + p * 256;
        int r = slot >> 3, c = slot & 7;
        int gr = q0 + r; if (gr > SEQ - 1) gr = SEQ - 1;
        size_t idx = ((hb + gr) << 6) + c * 8;
        uint32_t so = aswz(r, c);
        *(int4*)(sm + ATT_QH + so) = *(const int4*)(g_qh + idx);
        *(int4*)(sm + ATT_QL + so) = *(const int4*)(g_ql + idx);
    }
    __syncthreads();

    // Q fragments in registers (4 k16 steps over DH)
    uint32_t qh[4][4], ql[4][4];
    #pragma unroll
    for (int kd = 0; kd < 4; ++kd) {
        int row = w * 16 + (lane & 15);
        int c = 2 * kd + (lane >> 4);
        uint32_t o = aswz(row, c);
        ldsm_x4(qh[kd][0], qh[kd][1], qh[kd][2], qh[kd][3], sb + ATT_QH + o);
        ldsm_x4(ql[kd][0], ql[kd][1], ql[kd][2], ql[kd][3], sb + ATT_QL + o);
    }

    float o[8][4];
    #pragma unroll
    for (int i = 0; i < 8; ++i)
        #pragma unroll
        for (int j = 0; j < 4; ++j) o[i][j] = 0.f;
    float m0 = -1e30f, m1 = -1e30f, l0 = 0.f, l1 = 0.f;

    for (int kt = 0; kt < NKT; ++kt) {
        const int k0 = kt * KT;
        __syncthreads();
        #pragma unroll
        for (int p = 0; p < 4; ++p) {
            int slot = tid + p * 256;
            int r = slot >> 3, c = slot & 7;
            int gk = k0 + r; if (gk > SEQ - 1) gk = SEQ - 1;
            size_t idx = ((hb + gk) << 6) + c * 8;
            uint32_t so = aswz(r, c);
            *(int4*)(sm + ATT_KH + so) = *(const int4*)(g_kh + idx);
            *(int4*)(sm + ATT_KL + so) = *(const int4*)(g_kl + idx);
            *(int4*)(sm + ATT_VH + so) = *(const int4*)(g_vh + idx);
            *(int4*)(sm + ATT_VL + so) = *(const int4*)(g_vl + idx);
        }
        __syncthreads();

        // ---- S = Q K^T ----
        float s[16][4];
        #pragma unroll
        for (int i = 0; i < 16; ++i)
            #pragma unroll
            for (int j = 0; j < 4; ++j) s[i][j] = 0.f;

        #pragma unroll
        for (int kp = 0; kp < 8; ++kp) {
            #pragma unroll
            for (int kd = 0; kd < 4; ++kd) {
                int g = lane >> 3, li = lane & 7;
                int row = kp * 16 + ((g >> 1) << 3) + li;
                int c = 2 * kd + (g & 1);
                uint32_t so = aswz(row, c);
                uint32_t kh4[4], kl4[4];
                ldsm_x4(kh4[0], kh4[1], kh4[2], kh4[3], sb + ATT_KH + so);
                ldsm_x4(kl4[0], kl4[1], kl4[2], kl4[3], sb + ATT_KL + so);
                mma2(s[2*kp],   qh[kd], kh4[0], kh4[1]);
                mma2(s[2*kp],   qh[kd], kl4[0], kl4[1]);
                mma2(s[2*kp],   ql[kd], kh4[0], kh4[1]);
                mma2(s[2*kp+1], qh[kd], kh4[2], kh4[3]);
                mma2(s[2*kp+1], qh[kd], kl4[2], kl4[3]);
                mma2(s[2*kp+1], ql[kd], kh4[2], kh4[3]);
            }
        }

        // mask invalid keys (last tile)
        if (k0 + KT > SEQ) {
            #pragma unroll
            for (int kn = 0; kn < 16; ++kn) {
                int kg = k0 + kn * 8 + ((lane & 3) << 1);
                if (kg >= SEQ)     { s[kn][0] = -1e30f; s[kn][2] = -1e30f; }
                if (kg + 1 >= SEQ) { s[kn][1] = -1e30f; s[kn][3] = -1e30f; }
            }
        }

        // ---- online softmax ----
        float mx0 = -1e30f, mx1 = -1e30f;
        #pragma unroll
        for (int kn = 0; kn < 16; ++kn) {
            mx0 = fmaxf(mx0, fmaxf(s[kn][0], s[kn][1]));
            mx1 = fmaxf(mx1, fmaxf(s[kn][2], s[kn][3]));
        }
        mx0 = fmaxf(mx0, __shfl_xor_sync(0xffffffffu, mx0, 1));
        mx0 = fmaxf(mx0, __shfl_xor_sync(0xffffffffu, mx0, 2));
        mx1 = fmaxf(mx1, __shfl_xor_sync(0xffffffffu, mx1, 1));
        mx1 = fmaxf(mx1, __shfl_xor_sync(0xffffffffu, mx1, 2));
        float mn0 = fmaxf(m0, mx0), mn1 = fmaxf(m1, mx1);
        float c0 = __expf(m0 - mn0), c1 = __expf(m1 - mn1);
        float sum0 = 0.f, sum1 = 0.f;
        #pragma unroll
        for (int kn = 0; kn < 16; ++kn) {
            s[kn][0] = __expf(s[kn][0] - mn0);
            s[kn][1] = __expf(s[kn][1] - mn0);
            s[kn][2] = __expf(s[kn][2] - mn1);
            s[kn][3] = __expf(s[kn][3] - mn1);
            sum0 += s[kn][0] + s[kn][1];
            sum1 += s[kn][2] + s[kn][3];
        }
        sum0 += __shfl_xor_sync(0xffffffffu, sum0, 1);
        sum0 += __shfl_xor_sync(0xffffffffu, sum0, 2);
        sum1 += __shfl_xor_sync(0xffffffffu, sum1, 1);
        sum1 += __shfl_xor_sync(0xffffffffu, sum1, 2);
        l0 = l0 * c0 + sum0; l1 = l1 * c1 + sum1;
        m0 = mn0; m1 = mn1;
        #pragma unroll
        for (int nf = 0; nf < 8; ++nf) {
            o[nf][0] *= c0; o[nf][1] *= c0;
            o[nf][2] *= c1; o[nf][3] *= c1;
        }

        // ---- PV: O += P V  (P packed from S regs) ----
        #pragma unroll
        for (int kk = 0; kk < 8; ++kk) {
            uint32_t ah[4], al[4];
            split2(s[2*kk][0],   s[2*kk][1],   ah[0], al[0]);
            split2(s[2*kk][2],   s[2*kk][3],   ah[1], al[1]);
            split2(s[2*kk+1][0], s[2*kk+1][1], ah[2], al[2]);
            split2(s[2*kk+1][2], s[2*kk+1][3], ah[3], al[3]);
            #pragma unroll
            for (int d16 = 0; d16 < 4; ++d16) {
                int g = lane >> 3, li = lane & 7;
                int row = kk * 16 + ((g & 1) << 3) + li;
                int c = d16 * 2 + (g >> 1);
                uint32_t so = aswz(row, c);
                uint32_t vh4[4], vl4[4];
                ldsm_x4_t(vh4[0], vh4[1], vh4[2], vh4[3], sb + ATT_VH + so);
                ldsm_x4_t(vl4[0], vl4[1], vl4[2], vl4[3], sb + ATT_VL + so);
                mma2(o[2*d16],   ah, vh4[0], vh4[1]);
                mma2(o[2*d16],   al, vh4[0], vh4[1]);
                mma2(o[2*d16],   ah, vl4[0], vl4[1]);
                mma2(o[2*d16+1], ah, vh4[2], vh4[3]);
                mma2(o[2*d16+1], al, vh4[2], vh4[3]);
                mma2(o[2*d16+1], ah, vl4[2], vl4[3]);
            }
        }
    }

    // ---- epilogue: o/l -> bf16 hi/lo into proj-A buffers ----
    float r0 = 1.f / l0, r1 = 1.f / l1;
    int rg = lane >> 2, t2 = (lane & 3) << 1;
    int row0 = q0 + w * 16 + rg, row1 = row0 + 8;
    #pragma unroll
    for (int nf = 0; nf < 8; ++nf) {
        int col = hh * DH + nf * 8 + t2;
        if (row0 < SEQ) {
            size_t gi = (size_t)(b * SEQ + row0) * CH + col;
            uint32_t hp, lp;
            split2(o[nf][0] * r0, o[nf][1] * r0, hp, lp);
            *(uint32_t*)(g_xh + gi) = hp;
            *(uint32_t*)(g_xl + gi) = lp;
        }
        if (row1 < SEQ) {
            size_t gi = (size_t)(b * SEQ + row1) * CH + col;
            uint32_t hp, lp;
            split2(o[nf][2] * r1, o[nf][3] * r1, hp, lp);
            *(uint32_t*)(g_xh + gi) = hp;
            *(uint32_t*)(g_xl + gi) = lp;
        }
    }
}

// ---------------------------------------------------------------------------
extern "C" void kernel_launch(void* const* d_in, const int* in_sizes, int n_in,
                              void* d_out, int out_size)
{
    const float* x      = (const float*)d_in[0];
    const float* qkv_w  = (const float*)d_in[1];
    const float* qkv_b  = (const float*)d_in[2];
    const float* proj_w = (const float*)d_in[3];
    const float* proj_b = (const float*)d_in[4];
    float* out = (float*)d_out;

    cudaFuncSetAttribute(attn_mma, cudaFuncAttributeMaxDynamicSharedMemorySize, ATT_SMEM);

    split_kernel<<<(MROWS*CH + 255)/256, 256>>>(x, 0, MROWS*CH);
    split_kernel<<<(QKV_N*CH + 255)/256, 256>>>(qkv_w, 1, QKV_N*CH);
    split_kernel<<<(CH*CH + 255)/256, 256>>>(proj_w, 2, CH*CH);

    mma_gemm<0><<<dim3(QKV_N/128, (MROWS + 127)/128), 512>>>(qkv_b, nullptr);

    attn_mma<<<dim3((SEQ + QT - 1)/QT, NH, BN), 256, ATT_SMEM>>>();

    mma_gemm<1><<<dim3(CH/128, (MROWS + 127)/128), 512>>>(proj_b, out);
}